// round 3
// baseline (speedup 1.0000x reference)
#include <cuda_runtime.h>
#include <stdint.h>

// ---------------------------------------------------------------------------
// DynamicPointConvBackBone: only the first 2048 rows of each of B segments are
// observable through _resample -> compute gather+GEMM+LN+ReLU for 8192 rows only.
//
// Inputs (metadata order):
//   0: features     [N, 64]   f32
//   1: center_coors [M, 3]    f32
//   2: voxel_idx    [M, 27]   int32  (JAX silently downcasts int64 -> int32)
//   3: num_list     [B]       i32
//   4: W            [1728,128] f32
//   5: gamma        [128]     f32
//   6: beta         [128]     f32
//   7: num_keypoints (scalar) -- fixed at 2048
// Output: point_features [B*2048, 128] f32  then  point_coords [B*2048, 4] f32
// ---------------------------------------------------------------------------

#define K3      27
#define CIN     64
#define COUT    128
#define KP      2048      // num_keypoints
#define KP_LOG2 11
#define TR      64        // rows per CTA
#define NT      256       // threads per CTA
#define KC      32        // K-chunk (half a neighbor's 64 channels)
#define EPS     1e-3f

// packed fp32x2 FMA (Blackwell FFMA2; ptxas never emits this from C++)
#define FFMA2(d, a, b) \
    asm("fma.rn.f32x2 %0, %1, %2, %0;" : "+l"(d) : "l"(a), "l"(b))

__device__ __forceinline__ float2 unpack_f32x2(unsigned long long v) {
    float2 f;
    asm("mov.b64 {%0, %1}, %2;" : "=f"(f.x), "=f"(f.y) : "l"(v));
    return f;
}

__global__ __launch_bounds__(NT, 1)
void fused_gather_gemm_ln(const float* __restrict__ feat,
                          const int* __restrict__ vidx,
                          const float* __restrict__ W,
                          const float* __restrict__ gamma,
                          const float* __restrict__ beta,
                          const int* __restrict__ num_list,
                          float* __restrict__ out_feat,
                          int Nfeat, int M, int B, int totalRows)
{
    // static smem: A2 (duplicated) 64x64 f32 = 16KB, B chunk 32x128 f32 = 16KB,
    // idx 64x27 i32 = 6.75KB, src/valid 0.5KB  -> ~39.6KB  (< 48KB, no attr call)
    __shared__ float A2s[TR * (2 * KC)];   // row r: 32 local-K values duplicated -> 64 floats
    __shared__ float Bs[KC * COUT];        // [32][128]
    __shared__ int   idx_s[TR * K3];
    __shared__ int   src_s[TR];
    __shared__ int   val_s[TR];
    __shared__ int   nl_s[8];              // num_list broadcast (B <= 8)

    const int tid  = threadIdx.x;
    const int base = blockIdx.x * TR;

    if (tid == 0) {
        #pragma unroll 4
        for (int i = 0; i < B && i < 8; ++i) nl_s[i] = num_list[i];
    }
    __syncthreads();

    // --- per-row source voxel + validity -----------------------------------
    if (tid < TR) {
        int gr = base + tid;
        int src = 0, valid = 0;
        if (gr < totalRows) {
            int b = gr >> KP_LOG2;
            int j = gr & (KP - 1);
            int off = 0;
            #pragma unroll 4
            for (int i = 0; i < b; ++i) off += nl_s[i];
            int nl = nl_s[b];
            src = off + j;
            if (src > M - 1) src = M - 1;
            if (src < 0)     src = 0;
            valid = (j < nl) ? 1 : 0;
        }
        src_s[tid] = src;
        val_s[tid] = valid;
    }
    __syncthreads();

    // --- load + clip neighbor indices (int32; neg -> -1 sentinel) ----------
    for (int e = tid; e < TR * K3; e += NT) {
        int r = e / K3, k = e % K3;
        int raw = vidx[(size_t)src_s[r] * K3 + k];
        int v;
        if (raw < 0) v = -1;
        else {
            v = raw;
            if (v > Nfeat - 1) v = Nfeat - 1;
        }
        idx_s[e] = v;
    }

    // --- accumulators: 8 rows x 4 cols per thread, as f32x2 pairs ----------
    unsigned long long acc[8][2];
    #pragma unroll
    for (int i = 0; i < 8; ++i) { acc[i][0] = 0ull; acc[i][1] = 0ull; }

    const int ry = tid >> 5;        // warp id 0..7  -> rows ry*8 .. ry*8+7
    const int cx = tid & 31;        // lane          -> cols cx*4 .. cx*4+3
    const int r0 = ry * 8;

    // gather-load thread mapping
    const int g_c2 = tid & 15;      // float2 index within 32-channel half
    const int g_rq = tid >> 4;      // 0..15

    // --- main loop over 54 K-chunks (27 neighbors x 2 halves) --------------
    for (int h = 0; h < 2 * K3; ++h) {
        const int k    = h >> 1;
        const int half = h & 1;
        __syncthreads();

        // W chunk: rows [k*64 + half*32, +32) x 128 cols, coalesced float4 copy
        {
            const float4* Wg = (const float4*)(W + (size_t)(k * CIN + half * KC) * COUT);
            float4* Bv = (float4*)Bs;
            #pragma unroll
            for (int e = 0; e < 4; ++e) Bv[tid + e * NT] = Wg[tid + e * NT];
        }
        // A gather: 64 rows x 32 channels, stored duplicated (a,a) for f32x2
        {
            #pragma unroll
            for (int rp = 0; rp < 4; ++rp) {
                int r   = rp * 16 + g_rq;
                int fid = idx_s[r * K3 + k];
                float2 v;
                if (fid >= 0)
                    v = ((const float2*)(feat + (size_t)fid * CIN))[half * 16 + g_c2];
                else
                    v = make_float2(0.f, 0.f);
                ((float4*)(A2s + r * (2 * KC)))[g_c2] =
                    make_float4(v.x, v.x, v.y, v.y);
            }
        }
        __syncthreads();

        // compute: 16 steps x 2 K-values each
        #pragma unroll
        for (int u = 0; u < KC / 2; ++u) {
            ulonglong2 b0 = *(const ulonglong2*)(Bs + (2 * u)     * COUT + cx * 4);
            ulonglong2 b1 = *(const ulonglong2*)(Bs + (2 * u + 1) * COUT + cx * 4);
            #pragma unroll
            for (int i = 0; i < 8; ++i) {
                ulonglong2 a = *(const ulonglong2*)(A2s + (r0 + i) * (2 * KC) + u * 4);
                FFMA2(acc[i][0], a.x, b0.x);
                FFMA2(acc[i][1], a.x, b0.y);
                FFMA2(acc[i][0], a.y, b1.x);
                FFMA2(acc[i][1], a.y, b1.y);
            }
        }
    }

    // --- LayerNorm + ReLU epilogue: warp ry owns rows r0..r0+7 entirely ----
    float4 g  = ((const float4*)gamma)[cx];
    float4 bt = ((const float4*)beta)[cx];
    #pragma unroll
    for (int i = 0; i < 8; ++i) {
        float2 p0 = unpack_f32x2(acc[i][0]);   // cols cx*4, cx*4+1
        float2 p1 = unpack_f32x2(acc[i][1]);   // cols cx*4+2, cx*4+3
        float s  = p0.x + p0.y + p1.x + p1.y;
        float sq = p0.x * p0.x + p0.y * p0.y + p1.x * p1.x + p1.y * p1.y;
        #pragma unroll
        for (int o = 16; o > 0; o >>= 1) {
            s  += __shfl_xor_sync(0xffffffffu, s,  o);
            sq += __shfl_xor_sync(0xffffffffu, sq, o);
        }
        float mu  = s * (1.f / COUT);
        float var = sq * (1.f / COUT) - mu * mu;
        float inv = rsqrtf(var + EPS);
        int gr = base + r0 + i;
        if (gr < totalRows) {
            float4 o4;
            o4.x = fmaxf(0.f, (p0.x - mu) * inv * g.x + bt.x);
            o4.y = fmaxf(0.f, (p0.y - mu) * inv * g.y + bt.y);
            o4.z = fmaxf(0.f, (p1.x - mu) * inv * g.z + bt.z);
            o4.w = fmaxf(0.f, (p1.y - mu) * inv * g.w + bt.w);
            if (!val_s[r0 + i]) o4 = make_float4(0.f, 0.f, 0.f, 0.f);
            ((float4*)(out_feat + (size_t)gr * COUT))[cx] = o4;
        }
    }
}

__global__ void coords_kernel(const float* __restrict__ cc,
                              const int* __restrict__ num_list,
                              float* __restrict__ out_coor,
                              int M, int B, int totalRows)
{
    int r = blockIdx.x * blockDim.x + threadIdx.x;
    if (r >= totalRows) return;
    int b = r >> KP_LOG2;
    int j = r & (KP - 1);
    int off = 0;
    #pragma unroll 4
    for (int i = 0; i < b; ++i) off += __ldg(num_list + i);
    int nl  = __ldg(num_list + b);
    int src = off + j;
    if (src > M - 1) src = M - 1;
    if (src < 0)     src = 0;
    bool valid = (j < nl);
    // NOTE: reference writes col0 unconditionally; only xyz is masked by valid.
    float col0 = (b < B - 1) ? (float)(b + 1) : 0.f;
    float4 o;
    o.x = col0;
    if (valid) {
        o.y = cc[(size_t)src * 3 + 0];
        o.z = cc[(size_t)src * 3 + 1];
        o.w = cc[(size_t)src * 3 + 2];
    } else {
        o.y = 0.f; o.z = 0.f; o.w = 0.f;
    }
    ((float4*)out_coor)[r] = o;
}

extern "C" void kernel_launch(void* const* d_in, const int* in_sizes, int n_in,
                              void* d_out, int out_size)
{
    const float* feat     = (const float*)d_in[0];
    const float* cc       = (const float*)d_in[1];
    const int*   vidx     = (const int*)d_in[2];     // int32 (JAX x64 disabled)
    const int*   num_list = (const int*)d_in[3];
    const float* W        = (const float*)d_in[4];
    const float* gamma    = (const float*)d_in[5];
    const float* beta     = (const float*)d_in[6];

    int Nfeat = in_sizes[0] / CIN;   // 200000
    int M     = in_sizes[1] / 3;     // 40000
    int B     = in_sizes[3];         // 4
    int totalRows = B * KP;          // 8192

    float* out_feat = (float*)d_out;
    float* out_coor = out_feat + (size_t)totalRows * COUT;

    int gridMain = (totalRows + TR - 1) / TR;   // 128 CTAs
    fused_gather_gemm_ln<<<gridMain, NT>>>(feat, vidx, W, gamma, beta, num_list,
                                           out_feat, Nfeat, M, B, totalRows);

    int gridC = (totalRows + 255) / 256;
    coords_kernel<<<gridC, 256>>>(cc, num_list, out_coor, M, B, totalRows);
}

// round 5
// speedup vs baseline: 1.2870x; 1.2870x over previous
#include <cuda_runtime.h>
#include <stdint.h>

// ---------------------------------------------------------------------------
// DynamicPointConvBackBone: only the first 2048 rows of each of B segments are
// observable through _resample -> compute gather+GEMM+LN+ReLU for 8192 rows.
// Single fused kernel: gather + GEMM (FFMA2) + LayerNorm + ReLU + resample
// (features AND coords).
//
// Inputs: 0 features[N,64] f32 | 1 center_coors[M,3] f32 | 2 voxel_idx[M,27] i32
//         3 num_list[B] i32 | 4 W[1728,128] f32 | 5 gamma[128] | 6 beta[128]
// Output: point_features [8192,128] f32 ++ point_coords [8192,4] f32
// ---------------------------------------------------------------------------

#define K3      27
#define CIN     64
#define COUT    128
#define KP      2048
#define KP_LOG2 11
#define TR      64        // rows per CTA
#define NT      256       // threads per CTA
#define KC      32        // K-values per chunk (half a neighbor)
#define NCHUNK  (2 * K3)  // 54
#define EPS     1e-3f

// packed fp32x2 FMA (Blackwell FFMA2; ptxas never emits this from C++)
#define FFMA2(d, a, b) \
    asm("fma.rn.f32x2 %0, %1, %2, %0;" : "+l"(d) : "l"(a), "l"(b))

__device__ __forceinline__ float2 unpack_f32x2(unsigned long long v) {
    float2 f;
    asm("mov.b64 {%0, %1}, %2;" : "=f"(f.x), "=f"(f.y) : "l"(v));
    return f;
}

__global__ __launch_bounds__(NT)
void fused_gather_gemm_ln(const float* __restrict__ feat,
                          const int* __restrict__ vidx,
                          const float* __restrict__ W,
                          const float* __restrict__ gamma,
                          const float* __restrict__ beta,
                          const int* __restrict__ num_list,
                          const float* __restrict__ cc,
                          float* __restrict__ out_feat,
                          float* __restrict__ out_coor,
                          int Nfeat, int M, int B, int totalRows)
{
    // smem: A2s 64x64 f32 (dup) = 16KB, Bs 32x128 = 16KB, idx 6.75KB -> ~39.6KB
    __shared__ float A2s[TR * (2 * KC)];
    __shared__ float Bs[KC * COUT];
    __shared__ int   idx_s[TR * K3];
    __shared__ int   src_s[TR];
    __shared__ int   val_s[TR];
    __shared__ int   nl_s[8];

    const int tid  = threadIdx.x;
    const int base = blockIdx.x * TR;

    if (tid == 0) {
        #pragma unroll 4
        for (int i = 0; i < B && i < 8; ++i) nl_s[i] = num_list[i];
    }
    __syncthreads();

    // --- per-row source voxel + validity -----------------------------------
    if (tid < TR) {
        int gr = base + tid;
        int src = 0, valid = 0;
        if (gr < totalRows) {
            int b = gr >> KP_LOG2;
            int j = gr & (KP - 1);
            int off = 0;
            #pragma unroll 4
            for (int i = 0; i < b; ++i) off += nl_s[i];
            int nl = nl_s[b];
            src = off + j;
            if (src > M - 1) src = M - 1;
            if (src < 0)     src = 0;
            valid = (j < nl) ? 1 : 0;
        }
        src_s[tid] = src;
        val_s[tid] = valid;
    }
    __syncthreads();

    // --- neighbor indices (int32; neg -> -1 sentinel) ----------------------
    // TR*K3 = 1728 elements; each thread handles rows tid>>2, k-quarter tid&3
    {
        // simple strided loop, divide hoisted via precomputed reciprocal-free
        // mapping: e = r*K3 + k with r = e / 27 done once per 27-element run
        for (int r = tid >> 2; r < TR; r += NT >> 2) {
            const int kq = (tid & 3) * 7;                 // 0,7,14,21
            const int kend = (kq == 21) ? K3 : kq + 7;    // last quarter: 6 elems
            const int* row = vidx + (size_t)src_s[r] * K3;
            for (int k = kq; k < kend; ++k) {
                int raw = row[k];
                int v = raw;
                if (raw < 0) v = -1;
                else if (v > Nfeat - 1) v = Nfeat - 1;
                idx_s[r * K3 + k] = v;
            }
        }
    }
    __syncthreads();

    // --- accumulators: 8 rows x 4 cols per thread, as f32x2 pairs ----------
    unsigned long long acc[8][2];
    #pragma unroll
    for (int i = 0; i < 8; ++i) { acc[i][0] = 0ull; acc[i][1] = 0ull; }

    const int ry = tid >> 5;        // warp id -> rows ry*8..ry*8+7
    const int cx = tid & 31;        // lane    -> cols cx*4..cx*4+3
    const int r0 = ry * 8;

    // gather mapping: 8 lanes per row (float4 channel groups), 2 rows/thread
    const int g_g  = tid & 7;       // channel float4 group 0..7 (32 ch / chunk)
    const int g_r  = tid >> 3;      // row 0..31 (+32 for second)

    // --- register-prefetch pipeline ----------------------------------------
    float4 wreg[4];
    float4 areg[2];

    // prologue: load chunk 0
    {
        const float4* Wg = (const float4*)(W);
        #pragma unroll
        for (int e = 0; e < 4; ++e) wreg[e] = Wg[tid + e * NT];
        #pragma unroll
        for (int p = 0; p < 2; ++p) {
            int r   = g_r + p * 32;
            int fid = idx_s[r * K3 + 0];
            areg[p] = (fid >= 0)
                ? ((const float4*)(feat + (size_t)fid * CIN))[g_g]
                : make_float4(0.f, 0.f, 0.f, 0.f);
        }
    }

    for (int h = 0; h < NCHUNK; ++h) {
        __syncthreads();   // previous compute done reading smem

        // STS prefetched regs -> smem
        {
            float4* Bv = (float4*)Bs;
            #pragma unroll
            for (int e = 0; e < 4; ++e) Bv[tid + e * NT] = wreg[e];
            #pragma unroll
            for (int p = 0; p < 2; ++p) {
                int r = g_r + p * 32;
                float4 v = areg[p];
                float4* dst = (float4*)(A2s + r * (2 * KC) + g_g * 8);
                dst[0] = make_float4(v.x, v.x, v.y, v.y);
                dst[1] = make_float4(v.z, v.z, v.w, v.w);
            }
        }
        __syncthreads();   // smem ready

        // issue loads for chunk h+1 (latency hidden behind compute)
        if (h + 1 < NCHUNK) {
            int hn = h + 1;
            int kn = hn >> 1, halfn = hn & 1;
            const float4* Wg =
                (const float4*)(W + (size_t)(kn * CIN + halfn * KC) * COUT);
            #pragma unroll
            for (int e = 0; e < 4; ++e) wreg[e] = Wg[tid + e * NT];
            #pragma unroll
            for (int p = 0; p < 2; ++p) {
                int r   = g_r + p * 32;
                int fid = idx_s[r * K3 + kn];
                areg[p] = (fid >= 0)
                    ? ((const float4*)(feat + (size_t)fid * CIN))[halfn * 8 + g_g]
                    : make_float4(0.f, 0.f, 0.f, 0.f);
            }
        }

        // compute chunk h: 16 steps x 2 K-values
        #pragma unroll
        for (int u = 0; u < KC / 2; ++u) {
            ulonglong2 b0 = *(const ulonglong2*)(Bs + (2 * u)     * COUT + cx * 4);
            ulonglong2 b1 = *(const ulonglong2*)(Bs + (2 * u + 1) * COUT + cx * 4);
            #pragma unroll
            for (int i = 0; i < 8; ++i) {
                ulonglong2 a = *(const ulonglong2*)(A2s + (r0 + i) * (2 * KC) + u * 4);
                FFMA2(acc[i][0], a.x, b0.x);
                FFMA2(acc[i][1], a.x, b0.y);
                FFMA2(acc[i][0], a.y, b1.x);
                FFMA2(acc[i][1], a.y, b1.y);
            }
        }
    }

    // --- LayerNorm + ReLU epilogue -----------------------------------------
    float4 g  = ((const float4*)gamma)[cx];
    float4 bt = ((const float4*)beta)[cx];
    #pragma unroll
    for (int i = 0; i < 8; ++i) {
        float2 p0 = unpack_f32x2(acc[i][0]);
        float2 p1 = unpack_f32x2(acc[i][1]);
        float s  = p0.x + p0.y + p1.x + p1.y;
        float sq = p0.x * p0.x + p0.y * p0.y + p1.x * p1.x + p1.y * p1.y;
        #pragma unroll
        for (int o = 16; o > 0; o >>= 1) {
            s  += __shfl_xor_sync(0xffffffffu, s,  o);
            sq += __shfl_xor_sync(0xffffffffu, sq, o);
        }
        float mu  = s * (1.f / COUT);
        float var = sq * (1.f / COUT) - mu * mu;
        float inv = rsqrtf(var + EPS);
        int gr = base + r0 + i;
        if (gr < totalRows) {
            float4 o4;
            o4.x = fmaxf(0.f, (p0.x - mu) * inv * g.x + bt.x);
            o4.y = fmaxf(0.f, (p0.y - mu) * inv * g.y + bt.y);
            o4.z = fmaxf(0.f, (p1.x - mu) * inv * g.z + bt.z);
            o4.w = fmaxf(0.f, (p1.y - mu) * inv * g.w + bt.w);
            if (!val_s[r0 + i]) o4 = make_float4(0.f, 0.f, 0.f, 0.f);
            ((float4*)(out_feat + (size_t)gr * COUT))[cx] = o4;
        }
    }

    // --- coords: fused (row mapping identical; src/valid already in smem) ---
    if (tid < TR) {
        int gr = base + tid;
        if (gr < totalRows) {
            int b   = gr >> KP_LOG2;
            int src = src_s[tid];
            // col0 written unconditionally (reference quirk); xyz masked.
            float col0 = (b < B - 1) ? (float)(b + 1) : 0.f;
            float4 o;
            o.x = col0;
            if (val_s[tid]) {
                o.y = cc[(size_t)src * 3 + 0];
                o.z = cc[(size_t)src * 3 + 1];
                o.w = cc[(size_t)src * 3 + 2];
            } else {
                o.y = 0.f; o.z = 0.f; o.w = 0.f;
            }
            ((float4*)out_coor)[gr] = o;
        }
    }
}

extern "C" void kernel_launch(void* const* d_in, const int* in_sizes, int n_in,
                              void* d_out, int out_size)
{
    const float* feat     = (const float*)d_in[0];
    const float* cc       = (const float*)d_in[1];
    const int*   vidx     = (const int*)d_in[2];     // int32 (JAX x64 disabled)
    const int*   num_list = (const int*)d_in[3];
    const float* W        = (const float*)d_in[4];
    const float* gamma    = (const float*)d_in[5];
    const float* beta     = (const float*)d_in[6];

    int Nfeat = in_sizes[0] / CIN;   // 200000
    int M     = in_sizes[1] / 3;     // 40000
    int B     = in_sizes[3];         // 4
    int totalRows = B * KP;          // 8192

    float* out_feat = (float*)d_out;
    float* out_coor = out_feat + (size_t)totalRows * COUT;

    int gridMain = (totalRows + TR - 1) / TR;   // 128 CTAs
    fused_gather_gemm_ln<<<gridMain, NT>>>(feat, vidx, W, gamma, beta, num_list,
                                           cc, out_feat, out_coor,
                                           Nfeat, M, B, totalRows);
}

// round 6
// speedup vs baseline: 1.3144x; 1.0213x over previous
#include <cuda_runtime.h>
#include <stdint.h>

// ---------------------------------------------------------------------------
// DynamicPointConvBackBone fused kernel, dual-group split-K edition.
// 512 threads = 2 groups x 256. Group g computes K-range [g*864, (g+1)*864)
// of the 1728-deep GEMM for the same 64-row tile, using its own smem buffers
// and named barrier -> 16 warps/SM with independent pipelines.
// Group 1 spills partials to smem; group 0 reduces + LayerNorm + ReLU + coords.
// ---------------------------------------------------------------------------

#define K3      27
#define CIN     64
#define COUT    128
#define KP      2048
#define KP_LOG2 11
#define TR      64         // rows per CTA
#define NT      512        // 2 groups x 256
#define KC      16         // K-values per chunk (quarter neighbor)
#define NCHG    54         // chunks per group (54*16 = 864 = half of 1728)
#define ARS     36         // A row stride in floats (16 dup -> 32, +4 pad)
#define EPS     1e-3f

#define FFMA2(d, a, b) \
    asm("fma.rn.f32x2 %0, %1, %2, %0;" : "+l"(d) : "l"(a), "l"(b))
#define FADD2(d, a) \
    asm("add.rn.f32x2 %0, %0, %1;" : "+l"(d) : "l"(a))
#define BARG(gid) \
    asm volatile("bar.sync %0, 256;" :: "r"((gid) + 1) : "memory")

__device__ __forceinline__ float2 unpack_f32x2(unsigned long long v) {
    float2 f;
    asm("mov.b64 {%0, %1}, %2;" : "=f"(f.x), "=f"(f.y) : "l"(v));
    return f;
}

__global__ __launch_bounds__(NT, 1)
void fused_gather_gemm_ln(const float* __restrict__ feat,
                          const int* __restrict__ vidx,
                          const float* __restrict__ W,
                          const float* __restrict__ gamma,
                          const float* __restrict__ beta,
                          const int* __restrict__ num_list,
                          const float* __restrict__ cc,
                          float* __restrict__ out_feat,
                          float* __restrict__ out_coor,
                          int Nfeat, int M, int B, int totalRows)
{
    // pool: A bufs 2 x (64*36) = 4608 f | B bufs 2 x (16*128) = 4096 f
    // = 8704 floats (34.8KB). Reduction spill (64x128 = 8192 f) reuses pool.
    __shared__ float pool[2 * TR * ARS + 2 * KC * COUT];
    __shared__ int   idx_s[TR * K3];
    __shared__ int   src_s[TR];
    __shared__ int   val_s[TR];
    __shared__ int   nl_s[8];

    float* const Ag0 = pool;                       // group A bases
    float* const Bg0 = pool + 2 * TR * ARS;        // group B bases

    const int tid  = threadIdx.x;
    const int gid  = tid >> 8;          // group 0/1
    const int ltid = tid & 255;         // id within group
    const int base = blockIdx.x * TR;

    float* const Ag = Ag0 + gid * (TR * ARS);
    float* const Bg = Bg0 + gid * (KC * COUT);

    if (tid == 0) {
        #pragma unroll 4
        for (int i = 0; i < B && i < 8; ++i) nl_s[i] = num_list[i];
    }
    __syncthreads();

    // --- per-row source voxel + validity -----------------------------------
    if (tid < TR) {
        int gr = base + tid;
        int src = 0, valid = 0;
        if (gr < totalRows) {
            int b = gr >> KP_LOG2;
            int j = gr & (KP - 1);
            int off = 0;
            #pragma unroll 4
            for (int i = 0; i < b; ++i) off += nl_s[i];
            int nl = nl_s[b];
            src = off + j;
            if (src > M - 1) src = M - 1;
            if (src < 0)     src = 0;
            valid = (j < nl) ? 1 : 0;
        }
        src_s[tid] = src;
        val_s[tid] = valid;
    }
    __syncthreads();

    // --- neighbor indices (int32; neg -> -1 sentinel) ----------------------
    for (int r = tid >> 3; r < TR; r += NT >> 3) {
        const int k0 = (tid & 7) * 4;                  // 0,4,...,28
        const int k1 = (k0 == 24) ? K3 : k0 + 4;       // last slot covers 24..26
        if (k0 < K3) {
            const int* row = vidx + (size_t)src_s[r] * K3;
            for (int k = k0; k < k1; ++k) {
                int raw = row[k];
                int v = raw;
                if (raw < 0) v = -1;
                else if (v > Nfeat - 1) v = Nfeat - 1;
                idx_s[r * K3 + k] = v;
            }
        }
    }
    __syncthreads();

    // --- accumulators: 8 rows x 4 cols per thread ---------------------------
    unsigned long long acc[8][2];
    #pragma unroll
    for (int i = 0; i < 8; ++i) { acc[i][0] = 0ull; acc[i][1] = 0ull; }

    const int gw = (tid >> 5) & 7;      // warp-in-group -> rows gw*8..+7
    const int cx = tid & 31;            // lane -> cols cx*4..+3
    const int r0 = gw * 8;

    // gather mapping: 4 lanes per row (float4 groups over 16 channels)
    const int g_grp = ltid & 3;         // channel float4 group 0..3
    const int g_row = ltid >> 2;        // row 0..63

    float4 wreg[2];
    float4 areg;

    // prologue: prefetch chunk 0 of this group
    {
        int C = gid * NCHG;             // global chunk id
        int n = C >> 2, q = C & 3;
        const float4* Wg = (const float4*)(W + (size_t)(n * CIN + q * KC) * COUT);
        wreg[0] = Wg[ltid];
        wreg[1] = Wg[ltid + 256];
        int fid = idx_s[g_row * K3 + n];
        areg = (fid >= 0)
            ? ((const float4*)(feat + (size_t)fid * CIN))[q * 4 + g_grp]
            : make_float4(0.f, 0.f, 0.f, 0.f);
    }

    for (int c = 0; c < NCHG; ++c) {
        BARG(gid);   // previous compute done reading this group's buffers

        // STS prefetched regs -> smem
        {
            float4* Bv = (float4*)Bg;
            Bv[ltid]       = wreg[0];
            Bv[ltid + 256] = wreg[1];
            float4 v = areg;
            // duplicated A, row stride 36 floats (conflict-free per quarter-warp)
            float4* dst = (float4*)(Ag + g_row * ARS + g_grp * 8);
            dst[0] = make_float4(v.x, v.x, v.y, v.y);
            dst[1] = make_float4(v.z, v.z, v.w, v.w);
        }
        BARG(gid);   // buffers ready

        // prefetch chunk c+1
        if (c + 1 < NCHG) {
            int C = gid * NCHG + c + 1;
            int n = C >> 2, q = C & 3;
            const float4* Wg = (const float4*)(W + (size_t)(n * CIN + q * KC) * COUT);
            wreg[0] = Wg[ltid];
            wreg[1] = Wg[ltid + 256];
            int fid = idx_s[g_row * K3 + n];
            areg = (fid >= 0)
                ? ((const float4*)(feat + (size_t)fid * CIN))[q * 4 + g_grp]
                : make_float4(0.f, 0.f, 0.f, 0.f);
        }

        // compute chunk: 8 u-steps x 2 K-values
        #pragma unroll
        for (int u = 0; u < KC / 2; ++u) {
            ulonglong2 b0 = *(const ulonglong2*)(Bg + (2 * u)     * COUT + cx * 4);
            ulonglong2 b1 = *(const ulonglong2*)(Bg + (2 * u + 1) * COUT + cx * 4);
            #pragma unroll
            for (int i = 0; i < 8; ++i) {
                ulonglong2 a = *(const ulonglong2*)(Ag + (r0 + i) * ARS + u * 4);
                FFMA2(acc[i][0], a.x, b0.x);
                FFMA2(acc[i][1], a.x, b0.y);
                FFMA2(acc[i][0], a.y, b1.x);
                FFMA2(acc[i][1], a.y, b1.y);
            }
        }
    }

    // --- cross-group reduction: group1 spills, group0 adds ------------------
    __syncthreads();                    // all buffers dead; pool becomes Red
    float* const Red = pool;            // 64 x 128 floats
    if (gid == 1) {
        #pragma unroll
        for (int i = 0; i < 8; ++i) {
            ulonglong2 v; v.x = acc[i][0]; v.y = acc[i][1];
            *(ulonglong2*)(Red + (r0 + i) * COUT + cx * 4) = v;
        }
    }
    __syncthreads();

    if (gid == 0) {
        #pragma unroll
        for (int i = 0; i < 8; ++i) {
            ulonglong2 v = *(const ulonglong2*)(Red + (r0 + i) * COUT + cx * 4);
            FADD2(acc[i][0], v.x);
            FADD2(acc[i][1], v.y);
        }

        // --- LayerNorm + ReLU epilogue (group 0 only: 8 warps x 8 rows) ----
        float4 g  = ((const float4*)gamma)[cx];
        float4 bt = ((const float4*)beta)[cx];
        #pragma unroll
        for (int i = 0; i < 8; ++i) {
            float2 p0 = unpack_f32x2(acc[i][0]);
            float2 p1 = unpack_f32x2(acc[i][1]);
            float s  = p0.x + p0.y + p1.x + p1.y;
            float sq = p0.x * p0.x + p0.y * p0.y + p1.x * p1.x + p1.y * p1.y;
            #pragma unroll
            for (int o = 16; o > 0; o >>= 1) {
                s  += __shfl_xor_sync(0xffffffffu, s,  o);
                sq += __shfl_xor_sync(0xffffffffu, sq, o);
            }
            float mu  = s * (1.f / COUT);
            float var = sq * (1.f / COUT) - mu * mu;
            float inv = rsqrtf(var + EPS);
            int gr = base + r0 + i;
            if (gr < totalRows) {
                float4 o4;
                o4.x = fmaxf(0.f, (p0.x - mu) * inv * g.x + bt.x);
                o4.y = fmaxf(0.f, (p0.y - mu) * inv * g.y + bt.y);
                o4.z = fmaxf(0.f, (p1.x - mu) * inv * g.z + bt.z);
                o4.w = fmaxf(0.f, (p1.y - mu) * inv * g.w + bt.w);
                if (!val_s[r0 + i]) o4 = make_float4(0.f, 0.f, 0.f, 0.f);
                ((float4*)(out_feat + (size_t)gr * COUT))[cx] = o4;
            }
        }
    }

    // --- coords (group 0, first 64 threads; src/valid already in smem) ------
    if (tid < TR) {
        int gr = base + tid;
        if (gr < totalRows) {
            int b   = gr >> KP_LOG2;
            int src = src_s[tid];
            float col0 = (b < B - 1) ? (float)(b + 1) : 0.f;   // reference quirk
            float4 o;
            o.x = col0;
            if (val_s[tid]) {
                o.y = cc[(size_t)src * 3 + 0];
                o.z = cc[(size_t)src * 3 + 1];
                o.w = cc[(size_t)src * 3 + 2];
            } else {
                o.y = 0.f; o.z = 0.f; o.w = 0.f;
            }
            ((float4*)out_coor)[gr] = o;
        }
    }
}

extern "C" void kernel_launch(void* const* d_in, const int* in_sizes, int n_in,
                              void* d_out, int out_size)
{
    const float* feat     = (const float*)d_in[0];
    const float* cc       = (const float*)d_in[1];
    const int*   vidx     = (const int*)d_in[2];     // int32 (JAX x64 disabled)
    const int*   num_list = (const int*)d_in[3];
    const float* W        = (const float*)d_in[4];
    const float* gamma    = (const float*)d_in[5];
    const float* beta     = (const float*)d_in[6];

    int Nfeat = in_sizes[0] / CIN;   // 200000
    int M     = in_sizes[1] / 3;     // 40000
    int B     = in_sizes[3];         // 4
    int totalRows = B * KP;          // 8192

    float* out_feat = (float*)d_out;
    float* out_coor = out_feat + (size_t)totalRows * COUT;

    int gridMain = (totalRows + TR - 1) / TR;   // 128 CTAs
    fused_gather_gemm_ln<<<gridMain, NT>>>(feat, vidx, W, gamma, beta, num_list,
                                           cc, out_feat, out_coor,
                                           Nfeat, M, B, totalRows);
}